// round 3
// baseline (speedup 1.0000x reference)
#include <cuda_runtime.h>
#include <cstdint>

// Problem dims (fixed by the dataset)
#define D_MODEL 1024
#define SEQ     2048
#define BATCH   4
#define MROWS   (BATCH * SEQ)   // 8192

// ---------------- scratch (allocation-free rule: __device__ globals) ----------------
__device__ float g_Q [MROWS * D_MODEL];          // 32 MB, post-proj then post-LN (in place)
__device__ float g_K [MROWS * D_MODEL];          // 32 MB
__device__ float g_V [MROWS * D_MODEL];          // 32 MB, pre-LN V
__device__ float g_Vt[BATCH * D_MODEL * SEQ];    // 32 MB, LN(V) transposed: [b][d][s]
__device__ float g_S [BATCH * SEQ * SEQ];        // 64 MB, logits -> probs (in place)

// ---------------- helpers ----------------
__device__ __forceinline__ uint32_t f2tf32(float x) {
    uint32_t u;
    asm("cvt.rna.tf32.f32 %0, %1;" : "=r"(u) : "f"(x));
    return u;
}

// split a into big (tf32) + small (tf32 of residual); both reinterpretable as f32
__device__ __forceinline__ void tf32_split(float x, uint32_t& big, uint32_t& small) {
    big = f2tf32(x);
    float r = x - __uint_as_float(big);
    small = f2tf32(r);
}

__device__ __forceinline__ void mma8(float* c, const uint32_t* a, const uint32_t* b) {
    asm volatile(
        "mma.sync.aligned.m16n8k8.row.col.f32.tf32.tf32.f32 "
        "{%0,%1,%2,%3}, {%4,%5,%6,%7}, {%8,%9}, {%0,%1,%2,%3};\n"
        : "+f"(c[0]), "+f"(c[1]), "+f"(c[2]), "+f"(c[3])
        : "r"(a[0]), "r"(a[1]), "r"(a[2]), "r"(a[3]), "r"(b[0]), "r"(b[1]));
}

__device__ __forceinline__ float block_reduce_sum(float v, float* red) {
#pragma unroll
    for (int o = 16; o > 0; o >>= 1) v += __shfl_xor_sync(0xffffffffu, v, o);
    if ((threadIdx.x & 31) == 0) red[threadIdx.x >> 5] = v;
    __syncthreads();
    float tot = 0.f;
#pragma unroll
    for (int i = 0; i < 8; i++) tot += red[i];
    __syncthreads();
    return tot;
}

__device__ __forceinline__ float block_reduce_max(float v, float* red) {
#pragma unroll
    for (int o = 16; o > 0; o >>= 1) v = fmaxf(v, __shfl_xor_sync(0xffffffffu, v, o));
    if ((threadIdx.x & 31) == 0) red[threadIdx.x >> 5] = v;
    __syncthreads();
    float tot = -3.4e38f;
#pragma unroll
    for (int i = 0; i < 8; i++) tot = fmaxf(tot, red[i]);
    __syncthreads();
    return tot;
}

// ---------------- 3xTF32 GEMM core (fp32-accurate) ----------------
// C[m,n] = sum_k A[m,k] * B[n,k]  (+ bias[n])   — A, B row-major; "nk" form.
// Block tile 128x128, K-chunk 32, 256 threads (8 warps of 64x32 warp tiles).
// Smem holds raw fp32 (stride 36: conflict-free for float4 stores and fragment LDS).
// Fragments split into big/small tf32 at load; 3 MMAs per tile pair:
//   acc += Ab*Bb + Ab*Bs + As*Bb   (Markidis 3xTF32, ~21-bit effective mantissa)
__device__ __forceinline__ void gemm_core(
    const float* __restrict__ A, int lda,
    const float* __restrict__ Bm, int ldb,
    float* __restrict__ C, int ldc,
    int K, const float* __restrict__ bias)
{
    __shared__ float As[128][36];
    __shared__ float Bs[128][36];

    const int tid  = threadIdx.x;
    const int warp = tid >> 5, lane = tid & 31;
    const int g = lane >> 2, tg = lane & 3;
    const int wm0 = (warp >> 2) * 64;   // 0 or 64
    const int wn0 = (warp & 3) * 32;    // 0..96

    const int row0 = blockIdx.x * 128;
    const int n0   = blockIdx.y * 128;

    const float* Abase = A  + (size_t)row0 * lda;
    const float* Bbase = Bm + (size_t)n0   * ldb;

    float acc[4][4][4];
#pragma unroll
    for (int i = 0; i < 4; i++)
#pragma unroll
        for (int j = 0; j < 4; j++)
#pragma unroll
            for (int r = 0; r < 4; r++) acc[i][j][r] = 0.f;

    for (int k0 = 0; k0 < K; k0 += 32) {
#pragma unroll
        for (int i = 0; i < 4; i++) {
            int idx = tid + 256 * i;        // 0..1023
            int r   = idx >> 3;             // 0..127
            int c   = (idx & 7) << 2;       // 0,4,...,28
            *reinterpret_cast<float4*>(&As[r][c]) =
                *reinterpret_cast<const float4*>(Abase + (size_t)r * lda + k0 + c);
            *reinterpret_cast<float4*>(&Bs[r][c]) =
                *reinterpret_cast<const float4*>(Bbase + (size_t)r * ldb + k0 + c);
        }
        __syncthreads();

#pragma unroll
        for (int s = 0; s < 4; s++) {
            const int kb = s * 8;
            uint32_t afb[4][4], afs[4][4], bfb[4][2], bfs[4][2];
#pragma unroll
            for (int i = 0; i < 4; i++) {
                int m = wm0 + 16 * i;
                tf32_split(As[m + g    ][kb + tg    ], afb[i][0], afs[i][0]);
                tf32_split(As[m + g + 8][kb + tg    ], afb[i][1], afs[i][1]);
                tf32_split(As[m + g    ][kb + tg + 4], afb[i][2], afs[i][2]);
                tf32_split(As[m + g + 8][kb + tg + 4], afb[i][3], afs[i][3]);
            }
#pragma unroll
            for (int j = 0; j < 4; j++) {
                int n = wn0 + 8 * j;
                tf32_split(Bs[n + g][kb + tg    ], bfb[j][0], bfs[j][0]);
                tf32_split(Bs[n + g][kb + tg + 4], bfb[j][1], bfs[j][1]);
            }
#pragma unroll
            for (int i = 0; i < 4; i++)
#pragma unroll
                for (int j = 0; j < 4; j++) {
                    mma8(acc[i][j], afb[i], bfs[j]);   // big * small
                    mma8(acc[i][j], afs[i], bfb[j]);   // small * big
                    mma8(acc[i][j], afb[i], bfb[j]);   // big * big
                }
        }
        __syncthreads();
    }

    // epilogue
#pragma unroll
    for (int i = 0; i < 4; i++) {
        int m = row0 + wm0 + 16 * i;
#pragma unroll
        for (int j = 0; j < 4; j++) {
            int n = n0 + wn0 + 8 * j + 2 * tg;
            float b0 = 0.f, b1 = 0.f;
            if (bias) { b0 = bias[n]; b1 = bias[n + 1]; }
            float2 v0 = make_float2(acc[i][j][0] + b0, acc[i][j][1] + b1);
            float2 v1 = make_float2(acc[i][j][2] + b0, acc[i][j][3] + b1);
            *reinterpret_cast<float2*>(C + (size_t)(m + g    ) * ldc + n) = v0;
            *reinterpret_cast<float2*>(C + (size_t)(m + g + 8) * ldc + n) = v1;
        }
    }
}

// ---------------- kernels ----------------
// 1) QKV projection: Y = x @ W^T + b  (pre-LN), z selects {Q,K,V}
__global__ void __launch_bounds__(256, 2) proj_kernel(
    const float* __restrict__ x,
    const float* __restrict__ Wq, const float* __restrict__ bq,
    const float* __restrict__ Wk, const float* __restrict__ bk,
    const float* __restrict__ Wv, const float* __restrict__ bv)
{
    const float* W; const float* b; float* Cout;
    if (blockIdx.z == 0)      { W = Wq; b = bq; Cout = g_Q; }
    else if (blockIdx.z == 1) { W = Wk; b = bk; Cout = g_K; }
    else                      { W = Wv; b = bv; Cout = g_V; }
    gemm_core(x, D_MODEL, W, D_MODEL, Cout, D_MODEL, D_MODEL, b);
}

// 2) LayerNorm over D=1024. y=0/1: in-place on Q/K. y=2: LN(V) written transposed to g_Vt.
__global__ void __launch_bounds__(256) ln_kernel(
    const float* __restrict__ gamma, const float* __restrict__ beta)
{
    __shared__ float red[8];
    const int row   = blockIdx.x;   // 0..8191
    const int which = blockIdx.y;   // 0,1,2
    float* buf = (which == 0) ? g_Q : (which == 1) ? g_K : g_V;
    float* src = buf + (size_t)row * D_MODEL;
    const int t = threadIdx.x;

    float4 v = reinterpret_cast<const float4*>(src)[t];
    float s = v.x + v.y + v.z + v.w;
    s = block_reduce_sum(s, red);
    const float mean = s * (1.0f / D_MODEL);
    const float dx = v.x - mean, dy = v.y - mean, dz = v.z - mean, dw = v.w - mean;
    float sq = dx * dx + dy * dy + dz * dz + dw * dw;
    sq = block_reduce_sum(sq, red);
    const float rstd = rsqrtf(sq * (1.0f / D_MODEL) + 1e-5f);

    const float4 ga = reinterpret_cast<const float4*>(gamma)[t];
    const float4 be = reinterpret_cast<const float4*>(beta)[t];
    float4 o;
    o.x = dx * rstd * ga.x + be.x;
    o.y = dy * rstd * ga.y + be.y;
    o.z = dz * rstd * ga.z + be.z;
    o.w = dw * rstd * ga.w + be.w;

    if (which < 2) {
        reinterpret_cast<float4*>(src)[t] = o;
    } else {
        const int b  = row >> 11;        // /2048
        const int sI = row & 2047;
        float* vt = g_Vt + (size_t)b * (D_MODEL * SEQ) + sI;
        const int d0 = t * 4;
        vt[(size_t)(d0 + 0) * SEQ] = o.x;
        vt[(size_t)(d0 + 1) * SEQ] = o.y;
        vt[(size_t)(d0 + 2) * SEQ] = o.z;
        vt[(size_t)(d0 + 3) * SEQ] = o.w;
    }
}

// 3) S = Q @ K^T per batch (no scaling)
__global__ void __launch_bounds__(256, 2) qk_kernel()
{
    const size_t bz = blockIdx.z;
    gemm_core(g_Q + bz * SEQ * D_MODEL, D_MODEL,
              g_K + bz * SEQ * D_MODEL, D_MODEL,
              g_S + bz * SEQ * SEQ, SEQ,
              D_MODEL, nullptr);
}

// 4) row softmax over 2048 (in place)
__global__ void __launch_bounds__(256) softmax_kernel()
{
    __shared__ float red[8];
    const size_t row = (size_t)blockIdx.y * SEQ + blockIdx.x;
    float* p = g_S + row * SEQ;
    const int t = threadIdx.x;

    float4 u0 = reinterpret_cast<const float4*>(p)[t];
    float4 u1 = reinterpret_cast<const float4*>(p)[t + 256];
    float m = fmaxf(fmaxf(fmaxf(u0.x, u0.y), fmaxf(u0.z, u0.w)),
                    fmaxf(fmaxf(u1.x, u1.y), fmaxf(u1.z, u1.w)));
    m = block_reduce_max(m, red);

    u0.x = expf(u0.x - m); u0.y = expf(u0.y - m); u0.z = expf(u0.z - m); u0.w = expf(u0.w - m);
    u1.x = expf(u1.x - m); u1.y = expf(u1.y - m); u1.z = expf(u1.z - m); u1.w = expf(u1.w - m);
    float s = (u0.x + u0.y + u0.z + u0.w) + (u1.x + u1.y + u1.z + u1.w);
    s = block_reduce_sum(s, red);
    const float inv = 1.0f / s;

    u0.x *= inv; u0.y *= inv; u0.z *= inv; u0.w *= inv;
    u1.x *= inv; u1.y *= inv; u1.z *= inv; u1.w *= inv;
    reinterpret_cast<float4*>(p)[t]       = u0;
    reinterpret_cast<float4*>(p)[t + 256] = u1;
}

// 5) O = P @ V  == P(q,s) · Vt(d,s)^T per batch
__global__ void __launch_bounds__(256, 2) pv_kernel(float* __restrict__ out)
{
    const size_t bz = blockIdx.z;
    gemm_core(g_S  + bz * SEQ * SEQ, SEQ,
              g_Vt + bz * D_MODEL * SEQ, SEQ,
              out  + bz * SEQ * D_MODEL, D_MODEL,
              SEQ, nullptr);
}

// ---------------- launch ----------------
extern "C" void kernel_launch(void* const* d_in, const int* in_sizes, int n_in,
                              void* d_out, int out_size)
{
    const float* x     = (const float*)d_in[0];
    const float* Wq    = (const float*)d_in[1];
    const float* bq    = (const float*)d_in[2];
    const float* Wk    = (const float*)d_in[3];
    const float* bk    = (const float*)d_in[4];
    const float* Wv    = (const float*)d_in[5];
    const float* bv    = (const float*)d_in[6];
    const float* gamma = (const float*)d_in[7];
    const float* beta  = (const float*)d_in[8];
    float* out = (float*)d_out;

    dim3 tpb(256);
    proj_kernel   <<<dim3(MROWS / 128, D_MODEL / 128, 3), tpb>>>(x, Wq, bq, Wk, bk, Wv, bv);
    ln_kernel     <<<dim3(MROWS, 3), tpb>>>(gamma, beta);
    qk_kernel     <<<dim3(SEQ / 128, SEQ / 128, BATCH), tpb>>>();
    softmax_kernel<<<dim3(SEQ, BATCH), tpb>>>();
    pv_kernel     <<<dim3(SEQ / 128, D_MODEL / 128, BATCH), tpb>>>(out);
}

// round 5
// speedup vs baseline: 1.3434x; 1.3434x over previous
#include <cuda_runtime.h>
#include <cuda_bf16.h>
#include <cstdint>

// Problem dims (fixed by the dataset)
#define D_MODEL 1024
#define SEQ     2048
#define BATCH   4
#define MROWS   (BATCH * SEQ)   // 8192

// ---------------- scratch (allocation-free rule: __device__ globals) ----------------
__device__ float g_Q [MROWS * D_MODEL];          // 32 MB
__device__ float g_K [MROWS * D_MODEL];          // 32 MB
__device__ float g_V [MROWS * D_MODEL];          // 32 MB (pre-LN V)
__device__ float g_Vt[BATCH * D_MODEL * SEQ];    // 32 MB, LN(V) transposed: [b][d][s]
__device__ float g_S [BATCH * SEQ * SEQ];        // 64 MB, logits -> probs (in place)

// ---------------- helpers ----------------
// split two floats into packed bf16x2 big + bf16x2 small (Markidis-style)
__device__ __forceinline__ void bf16_split_pack(float x0, float x1,
                                                uint32_t& big, uint32_t& small) {
    __nv_bfloat16 b0 = __float2bfloat16(x0);
    __nv_bfloat16 b1 = __float2bfloat16(x1);
    float r0 = x0 - __bfloat162float(b0);
    float r1 = x1 - __bfloat162float(b1);
    __nv_bfloat16 s0 = __float2bfloat16(r0);
    __nv_bfloat16 s1 = __float2bfloat16(r1);
    __nv_bfloat162 bb = __halves2bfloat162(b0, b1);
    __nv_bfloat162 ss = __halves2bfloat162(s0, s1);
    big   = *reinterpret_cast<uint32_t*>(&bb);
    small = *reinterpret_cast<uint32_t*>(&ss);
}

__device__ __forceinline__ void mma16(float* c, const uint32_t* a, const uint32_t* b) {
    asm volatile(
        "mma.sync.aligned.m16n8k16.row.col.f32.bf16.bf16.f32 "
        "{%0,%1,%2,%3}, {%4,%5,%6,%7}, {%8,%9}, {%0,%1,%2,%3};\n"
        : "+f"(c[0]), "+f"(c[1]), "+f"(c[2]), "+f"(c[3])
        : "r"(a[0]), "r"(a[1]), "r"(a[2]), "r"(a[3]), "r"(b[0]), "r"(b[1]));
}

__device__ __forceinline__ float block_reduce_sum(float v, float* red) {
#pragma unroll
    for (int o = 16; o > 0; o >>= 1) v += __shfl_xor_sync(0xffffffffu, v, o);
    if ((threadIdx.x & 31) == 0) red[threadIdx.x >> 5] = v;
    __syncthreads();
    float tot = 0.f;
#pragma unroll
    for (int i = 0; i < 8; i++) tot += red[i];
    __syncthreads();
    return tot;
}

__device__ __forceinline__ float block_reduce_max(float v, float* red) {
#pragma unroll
    for (int o = 16; o > 0; o >>= 1) v = fmaxf(v, __shfl_xor_sync(0xffffffffu, v, o));
    if ((threadIdx.x & 31) == 0) red[threadIdx.x >> 5] = v;
    __syncthreads();
    float tot = -3.4e38f;
#pragma unroll
    for (int i = 0; i < 8; i++) tot = fmaxf(tot, red[i]);
    __syncthreads();
    return tot;
}

// ---------------- 3xBF16 GEMM core (fp32-accurate via error compensation) ----------------
// C[m,n] = sum_k A[m,k] * B[n,k]  (+ bias[n])   — A, B row-major; "nk" form.
// Block tile 128x128, K-chunk 32, 256 threads (8 warps of 64x32 warp tiles).
// Smem holds raw fp32 (stride 36: conflict-free float4 stores and fragment LDS).
// Fragments split into big/small bf16 at load; per k16 step, 3 MMAs per tile pair:
//   acc += Ab*Bs + As*Bb + Ab*Bb     (dropped As*Bs term ~2^-18 relative)
__device__ __forceinline__ void gemm_core(
    const float* __restrict__ A, int lda,
    const float* __restrict__ Bm, int ldb,
    float* __restrict__ C, int ldc,
    int K, const float* __restrict__ bias)
{
    __shared__ float As[128][36];
    __shared__ float Bs[128][36];

    const int tid  = threadIdx.x;
    const int warp = tid >> 5, lane = tid & 31;
    const int g = lane >> 2, tg = lane & 3;
    const int wm0 = (warp >> 2) * 64;   // 0 or 64
    const int wn0 = (warp & 3) * 32;    // 0..96

    const int row0 = blockIdx.x * 128;
    const int n0   = blockIdx.y * 128;

    const float* Abase = A  + (size_t)row0 * lda;
    const float* Bbase = Bm + (size_t)n0   * ldb;

    float acc[4][4][4];
#pragma unroll
    for (int i = 0; i < 4; i++)
#pragma unroll
        for (int j = 0; j < 4; j++)
#pragma unroll
            for (int r = 0; r < 4; r++) acc[i][j][r] = 0.f;

    for (int k0 = 0; k0 < K; k0 += 32) {
#pragma unroll
        for (int i = 0; i < 4; i++) {
            int idx = tid + 256 * i;        // 0..1023
            int r   = idx >> 3;             // 0..127
            int c   = (idx & 7) << 2;       // 0,4,...,28
            *reinterpret_cast<float4*>(&As[r][c]) =
                *reinterpret_cast<const float4*>(Abase + (size_t)r * lda + k0 + c);
            *reinterpret_cast<float4*>(&Bs[r][c]) =
                *reinterpret_cast<const float4*>(Bbase + (size_t)r * ldb + k0 + c);
        }
        __syncthreads();

#pragma unroll
        for (int s = 0; s < 2; s++) {           // two k16 steps per k32 chunk
            const int kb = s * 16;
            const int c0 = kb + 2 * tg;         // k 0..7 half
            const int c1 = kb + 8 + 2 * tg;     // k 8..15 half
            uint32_t afb[4][4], afs[4][4], bfb[4][2], bfs[4][2];
#pragma unroll
            for (int i = 0; i < 4; i++) {
                int m = wm0 + 16 * i;
                bf16_split_pack(As[m + g    ][c0], As[m + g    ][c0 + 1], afb[i][0], afs[i][0]);
                bf16_split_pack(As[m + g + 8][c0], As[m + g + 8][c0 + 1], afb[i][1], afs[i][1]);
                bf16_split_pack(As[m + g    ][c1], As[m + g    ][c1 + 1], afb[i][2], afs[i][2]);
                bf16_split_pack(As[m + g + 8][c1], As[m + g + 8][c1 + 1], afb[i][3], afs[i][3]);
            }
#pragma unroll
            for (int j = 0; j < 4; j++) {
                int n = wn0 + 8 * j;
                bf16_split_pack(Bs[n + g][c0], Bs[n + g][c0 + 1], bfb[j][0], bfs[j][0]);
                bf16_split_pack(Bs[n + g][c1], Bs[n + g][c1 + 1], bfb[j][1], bfs[j][1]);
            }
#pragma unroll
            for (int i = 0; i < 4; i++)
#pragma unroll
                for (int j = 0; j < 4; j++) {
                    mma16(acc[i][j], afb[i], bfs[j]);   // big  * small
                    mma16(acc[i][j], afs[i], bfb[j]);   // small* big
                    mma16(acc[i][j], afb[i], bfb[j]);   // big  * big
                }
        }
        __syncthreads();
    }

    // epilogue
#pragma unroll
    for (int i = 0; i < 4; i++) {
        int m = row0 + wm0 + 16 * i;
#pragma unroll
        for (int j = 0; j < 4; j++) {
            int n = n0 + wn0 + 8 * j + 2 * tg;
            float b0 = 0.f, b1 = 0.f;
            if (bias) { b0 = bias[n]; b1 = bias[n + 1]; }
            float2 v0 = make_float2(acc[i][j][0] + b0, acc[i][j][1] + b1);
            float2 v1 = make_float2(acc[i][j][2] + b0, acc[i][j][3] + b1);
            *reinterpret_cast<float2*>(C + (size_t)(m + g    ) * ldc + n) = v0;
            *reinterpret_cast<float2*>(C + (size_t)(m + g + 8) * ldc + n) = v1;
        }
    }
}

// ---------------- kernels ----------------
// 1) QKV projection: Y = x @ W^T + b  (pre-LN), z selects {Q,K,V}
__global__ void __launch_bounds__(256, 2) proj_kernel(
    const float* __restrict__ x,
    const float* __restrict__ Wq, const float* __restrict__ bq,
    const float* __restrict__ Wk, const float* __restrict__ bk,
    const float* __restrict__ Wv, const float* __restrict__ bv)
{
    const float* W; const float* b; float* Cout;
    if (blockIdx.z == 0)      { W = Wq; b = bq; Cout = g_Q; }
    else if (blockIdx.z == 1) { W = Wk; b = bk; Cout = g_K; }
    else                      { W = Wv; b = bv; Cout = g_V; }
    gemm_core(x, D_MODEL, W, D_MODEL, Cout, D_MODEL, D_MODEL, b);
}

// 2) LayerNorm over D=1024. y=0/1: in-place on Q/K. y=2: LN(V) written transposed to g_Vt.
__global__ void __launch_bounds__(256) ln_kernel(
    const float* __restrict__ gamma, const float* __restrict__ beta)
{
    __shared__ float red[8];
    const int row   = blockIdx.x;   // 0..8191
    const int which = blockIdx.y;   // 0,1,2
    float* buf = (which == 0) ? g_Q : (which == 1) ? g_K : g_V;
    float* src = buf + (size_t)row * D_MODEL;
    const int t = threadIdx.x;

    float4 v = reinterpret_cast<const float4*>(src)[t];
    float s = v.x + v.y + v.z + v.w;
    s = block_reduce_sum(s, red);
    const float mean = s * (1.0f / D_MODEL);
    const float dx = v.x - mean, dy = v.y - mean, dz = v.z - mean, dw = v.w - mean;
    float sq = dx * dx + dy * dy + dz * dz + dw * dw;
    sq = block_reduce_sum(sq, red);
    const float rstd = rsqrtf(sq * (1.0f / D_MODEL) + 1e-5f);

    const float4 ga = reinterpret_cast<const float4*>(gamma)[t];
    const float4 be = reinterpret_cast<const float4*>(beta)[t];
    float4 o;
    o.x = dx * rstd * ga.x + be.x;
    o.y = dy * rstd * ga.y + be.y;
    o.z = dz * rstd * ga.z + be.z;
    o.w = dw * rstd * ga.w + be.w;

    if (which < 2) {
        reinterpret_cast<float4*>(src)[t] = o;
    } else {
        const int b  = row >> 11;        // /2048
        const int sI = row & 2047;
        float* vt = g_Vt + (size_t)b * (D_MODEL * SEQ) + sI;
        const int d0 = t * 4;
        vt[(size_t)(d0 + 0) * SEQ] = o.x;
        vt[(size_t)(d0 + 1) * SEQ] = o.y;
        vt[(size_t)(d0 + 2) * SEQ] = o.z;
        vt[(size_t)(d0 + 3) * SEQ] = o.w;
    }
}

// 3) S = Q @ K^T per batch (no scaling)
__global__ void __launch_bounds__(256, 2) qk_kernel()
{
    const size_t bz = blockIdx.z;
    gemm_core(g_Q + bz * SEQ * D_MODEL, D_MODEL,
              g_K + bz * SEQ * D_MODEL, D_MODEL,
              g_S + bz * SEQ * SEQ, SEQ,
              D_MODEL, nullptr);
}

// 4) row softmax over 2048 (in place)
__global__ void __launch_bounds__(256) softmax_kernel()
{
    __shared__ float red[8];
    const size_t row = (size_t)blockIdx.y * SEQ + blockIdx.x;
    float* p = g_S + row * SEQ;
    const int t = threadIdx.x;

    float4 u0 = reinterpret_cast<const float4*>(p)[t];
    float4 u1 = reinterpret_cast<const float4*>(p)[t + 256];
    float m = fmaxf(fmaxf(fmaxf(u0.x, u0.y), fmaxf(u0.z, u0.w)),
                    fmaxf(fmaxf(u1.x, u1.y), fmaxf(u1.z, u1.w)));
    m = block_reduce_max(m, red);

    u0.x = expf(u0.x - m); u0.y = expf(u0.y - m); u0.z = expf(u0.z - m); u0.w = expf(u0.w - m);
    u1.x = expf(u1.x - m); u1.y = expf(u1.y - m); u1.z = expf(u1.z - m); u1.w = expf(u1.w - m);
    float s = (u0.x + u0.y + u0.z + u0.w) + (u1.x + u1.y + u1.z + u1.w);
    s = block_reduce_sum(s, red);
    const float inv = 1.0f / s;

    u0.x *= inv; u0.y *= inv; u0.z *= inv; u0.w *= inv;
    u1.x *= inv; u1.y *= inv; u1.z *= inv; u1.w *= inv;
    reinterpret_cast<float4*>(p)[t]       = u0;
    reinterpret_cast<float4*>(p)[t + 256] = u1;
}

// 5) O = P @ V  == P(q,s) · Vt(d,s)^T per batch
__global__ void __launch_bounds__(256, 2) pv_kernel(float* __restrict__ out)
{
    const size_t bz = blockIdx.z;
    gemm_core(g_S  + bz * SEQ * SEQ, SEQ,
              g_Vt + bz * D_MODEL * SEQ, SEQ,
              out  + bz * SEQ * D_MODEL, D_MODEL,
              SEQ, nullptr);
}

// ---------------- launch ----------------
extern "C" void kernel_launch(void* const* d_in, const int* in_sizes, int n_in,
                              void* d_out, int out_size)
{
    const float* x     = (const float*)d_in[0];
    const float* Wq    = (const float*)d_in[1];
    const float* bq    = (const float*)d_in[2];
    const float* Wk    = (const float*)d_in[3];
    const float* bk    = (const float*)d_in[4];
    const float* Wv    = (const float*)d_in[5];
    const float* bv    = (const float*)d_in[6];
    const float* gamma = (const float*)d_in[7];
    const float* beta  = (const float*)d_in[8];
    float* out = (float*)d_out;

    dim3 tpb(256);
    proj_kernel   <<<dim3(MROWS / 128, D_MODEL / 128, 3), tpb>>>(x, Wq, bq, Wk, bk, Wv, bv);
    ln_kernel     <<<dim3(MROWS, 3), tpb>>>(gamma, beta);
    qk_kernel     <<<dim3(SEQ / 128, SEQ / 128, BATCH), tpb>>>();
    softmax_kernel<<<dim3(SEQ, BATCH), tpb>>>();
    pv_kernel     <<<dim3(SEQ / 128, D_MODEL / 128, BATCH), tpb>>>(out);
}